// round 9
// baseline (speedup 1.0000x reference)
#include <cuda_runtime.h>
#include <cuda_bf16.h>

// BPMLL loss, factorized:
//   inner[b]  = (sum_{t==0} exp(x)) * (sum_{t==1} exp(-x))
//   length[b] = n_pos * n_neg
//   out       = sum_b inner[b] / length[b]
//
// B = 128, L = 1024, target int32.
//
// R9: TWO WARPS PER ROW. grid = 128 blocks x 64 threads. Halves the
// single-warp mainloop (16 elems/thread: 4x float4 + 4x int4, MLP=8 per
// thread) vs R8; pays one minimal cross-warp exchange (3 smem words +
// bar.sync). Reduce = interleaved f32 shfl chains + REDUX.SUM.U32.
// Finish: single u64 fixed-point atomic per row (low 56 bits = 2^32
// fixed-point loss sum, high 8 bits = arrival counter) -> bit-deterministic.

__device__ unsigned long long g_acc = 0ULL;

#define CNT_ONE   (1ULL << 56)
#define VAL_MASK  (CNT_ONE - 1ULL)
#define FP_SCALE  4294967296.0   // 2^32

__global__ void __launch_bounds__(64, 1)
bpmll_warp2_kernel(const float* __restrict__ inp,
                   const int* __restrict__ tgt,
                   float* __restrict__ out,
                   int L, int B) {
    const int b   = blockIdx.x;
    const int tid = threadIdx.x;   // 0..63
    const int lid = tid & 31;
    const int w   = tid >> 5;      // warp 0 or 1
    const float4* __restrict__ x4 = (const float4*)(inp + (size_t)b * L);
    const int4*   __restrict__ t4 = (const int4*)(tgt + (size_t)b * L);

    // L=1024 -> 256 float4 per row -> 4 per thread. Front-batch all loads.
    float4 v[4];
    int4   t[4];
    #pragma unroll
    for (int k = 0; k < 4; ++k) {
        v[k] = x4[tid + 64 * k];
        t[k] = t4[tid + 64 * k];
    }

    float s_neg  = 0.0f;   // sum exp(x) over negatives
    float s_pinv = 0.0f;   // sum exp(-x) over positives
    unsigned int np = 0u;  // positives count (targets are 0/1)

    #pragma unroll
    for (int k = 0; k < 4; ++k) {
        {
            bool p = (t[k].x == 1); float e = __expf(p ? -v[k].x : v[k].x);
            s_pinv += p ? e : 0.0f; s_neg += p ? 0.0f : e; np += (unsigned)t[k].x;
        }
        {
            bool p = (t[k].y == 1); float e = __expf(p ? -v[k].y : v[k].y);
            s_pinv += p ? e : 0.0f; s_neg += p ? 0.0f : e; np += (unsigned)t[k].y;
        }
        {
            bool p = (t[k].z == 1); float e = __expf(p ? -v[k].z : v[k].z);
            s_pinv += p ? e : 0.0f; s_neg += p ? 0.0f : e; np += (unsigned)t[k].z;
        }
        {
            bool p = (t[k].w == 1); float e = __expf(p ? -v[k].w : v[k].w);
            s_pinv += p ? e : 0.0f; s_neg += p ? 0.0f : e; np += (unsigned)t[k].w;
        }
    }

    // n_pos: single-instruction integer warp reduction
    np = __reduce_add_sync(0xffffffffu, np);

    // interleaved f32 shfl-xor chains
    #pragma unroll
    for (int off = 16; off > 0; off >>= 1) {
        s_neg  += __shfl_xor_sync(0xffffffffu, s_neg,  off);
        s_pinv += __shfl_xor_sync(0xffffffffu, s_pinv, off);
    }

    // minimal cross-warp exchange: warp 1 publishes, warp 0 lane 0 combines
    __shared__ float sh_n1, sh_p1;
    __shared__ unsigned int sh_np1;
    if (w == 1 && lid == 0) { sh_n1 = s_neg; sh_p1 = s_pinv; sh_np1 = np; }
    __syncthreads();

    if (tid == 0) {
        float tn = s_neg  + sh_n1;
        float tp = s_pinv + sh_p1;
        unsigned int n = np + sh_np1;

        float fnp = (float)n;
        float fnn = (float)L - fnp;
        float loss = (tn * tp) / (fnp * fnn);

        unsigned long long myval =
            (unsigned long long)llrint((double)loss * FP_SCALE) + CNT_ONE;
        unsigned long long old = atomicAdd(&g_acc, myval);

        if ((old >> 56) == (unsigned long long)(B - 1)) {
            unsigned long long total = (old + myval) & VAL_MASK;
            out[0] = (float)((double)total * (1.0 / FP_SCALE));
            g_acc = 0ULL;   // reset for next graph replay
        }
    }
}

extern "C" void kernel_launch(void* const* d_in, const int* in_sizes, int n_in,
                              void* d_out, int out_size) {
    const float* inp = (const float*)d_in[0];
    const int*   tgt = (const int*)d_in[1];
    float* out = (float*)d_out;

    const int B = 128;
    const int L = in_sizes[0] / B;   // 1024

    bpmll_warp2_kernel<<<B, 64>>>(inp, tgt, out, L, B);
}

// round 10
// speedup vs baseline: 1.0288x; 1.0288x over previous
#include <cuda_runtime.h>
#include <cuda_bf16.h>

// BPMLL loss, factorized:
//   inner[b]  = (sum_{t==0} exp(x)) * (sum_{t==1} exp(-x))
//   length[b] = n_pos * n_neg
//   out       = sum_b inner[b] / length[b]
//
// B = 128, L = 1024, target int32.
//
// R10: R8 mainloop (one warp per row, 128 x 32, front-batched float4/int4
// loads, branchless __expf, REDUX.SUM.U32 + shfl reduce) with a
// SPREAD-ADDRESS atomic finish to break same-address L2 atomic
// serialization: 8 fixed-point u64 slot accumulators on distinct L2 lines
// (<=16 contenders each) + one arrival counter. The 128th arriver sums the
// slots and stores. Integer adds everywhere -> bit-deterministic.

struct __align__(256) Slot { unsigned long long v; unsigned long long pad[31]; };
__device__ Slot g_slot[8];            // zero-initialized; reset by last block
__device__ unsigned int g_cnt = 0;

#define FP_SCALE  4294967296.0   // 2^32

__global__ void __launch_bounds__(32, 1)
bpmll_warp_kernel(const float* __restrict__ inp,
                  const int* __restrict__ tgt,
                  float* __restrict__ out,
                  int L, int B) {
    const int b   = blockIdx.x;
    const int lid = threadIdx.x;   // 0..31
    const float4* __restrict__ x4 = (const float4*)(inp + (size_t)b * L);
    const int4*   __restrict__ t4 = (const int4*)(tgt + (size_t)b * L);

    // L=1024 -> 256 float4 per row -> 8 per lane. Front-batch all loads
    // (16 outstanding LDG.128 per lane for max MLP).
    float4 v[8];
    int4   t[8];
    #pragma unroll
    for (int k = 0; k < 8; ++k) {
        v[k] = x4[lid + 32 * k];
        t[k] = t4[lid + 32 * k];
    }

    float s_neg  = 0.0f;   // sum exp(x) over negatives
    float s_pinv = 0.0f;   // sum exp(-x) over positives
    unsigned int np = 0u;  // positives count (targets are 0/1)

    #pragma unroll
    for (int k = 0; k < 8; ++k) {
        {
            bool p = (t[k].x == 1); float e = __expf(p ? -v[k].x : v[k].x);
            s_pinv += p ? e : 0.0f; s_neg += p ? 0.0f : e; np += (unsigned)t[k].x;
        }
        {
            bool p = (t[k].y == 1); float e = __expf(p ? -v[k].y : v[k].y);
            s_pinv += p ? e : 0.0f; s_neg += p ? 0.0f : e; np += (unsigned)t[k].y;
        }
        {
            bool p = (t[k].z == 1); float e = __expf(p ? -v[k].z : v[k].z);
            s_pinv += p ? e : 0.0f; s_neg += p ? 0.0f : e; np += (unsigned)t[k].z;
        }
        {
            bool p = (t[k].w == 1); float e = __expf(p ? -v[k].w : v[k].w);
            s_pinv += p ? e : 0.0f; s_neg += p ? 0.0f : e; np += (unsigned)t[k].w;
        }
    }

    // n_pos: single-instruction integer warp reduction
    np = __reduce_add_sync(0xffffffffu, np);

    // interleaved f32 shfl-xor chains
    #pragma unroll
    for (int off = 16; off > 0; off >>= 1) {
        s_neg  += __shfl_xor_sync(0xffffffffu, s_neg,  off);
        s_pinv += __shfl_xor_sync(0xffffffffu, s_pinv, off);
    }

    if (lid == 0) {
        float fnp = (float)np;
        float fnn = (float)L - fnp;
        float loss = (s_neg * s_pinv) / (fnp * fnn);

        unsigned long long fixed =
            (unsigned long long)llrint((double)loss * FP_SCALE);

        // level 1: spread-address accumulate (8 slots, distinct L2 lines)
        atomicAdd(&g_slot[b & 7].v, fixed);
        __threadfence();
        // level 2: arrival counter
        unsigned int old = atomicAdd(&g_cnt, 1u);

        if (old == (unsigned int)(B - 1)) {
            // all slot adds are visible (each predecessor fenced before its
            // counter bump; our counter read-modify-write ordered after them)
            unsigned long long total = 0ULL;
            #pragma unroll
            for (int i = 0; i < 8; ++i) {
                total += *(volatile unsigned long long*)&g_slot[i].v;
                g_slot[i].v = 0ULL;          // reset for next graph replay
            }
            out[0] = (float)((double)total * (1.0 / FP_SCALE));
            g_cnt = 0u;                      // reset for next graph replay
        }
    }
}

extern "C" void kernel_launch(void* const* d_in, const int* in_sizes, int n_in,
                              void* d_out, int out_size) {
    const float* inp = (const float*)d_in[0];
    const int*   tgt = (const int*)d_in[1];
    float* out = (float*)d_out;

    const int B = 128;
    const int L = in_sizes[0] / B;   // 1024

    bpmll_warp_kernel<<<B, 32>>>(inp, tgt, out, L, B);
}